// round 1
// baseline (speedup 1.0000x reference)
#include <cuda_runtime.h>

// ---------------------------------------------------------------------------
// BUIR / LightGCN forward.
// Strategy:
//   1. Counting-sort edges into CSR (histogram + 2-level scan + scatter).
//   2. Per encoding (online/target): X1 = A@ego, X2 = A@X1 (full SpMM,
//      gather-only, warp-per-row), then layer-3 only at the 8192 sampled
//      rows fused with acc = (ego + X1 + X2 + X3)/4.
//   3. online acc goes through the 64x64 linear head; target acc is written
//      straight to the output.
// Output layout: [u_pred | u_target | i_pred | i_target], each [B,64] f32.
// ---------------------------------------------------------------------------

#define D        64
#define D2       32          // float2 per embedding row
#define N_NODES  300000
#define NNZ_MAX  6400000
#define B_MAX    4096

// Scratch (device globals — no allocation allowed in kernel_launch)
__device__ int   g_counts[N_NODES];
__device__ int   g_rowptr[N_NODES + 1];
__device__ int   g_cursor[N_NODES];
__device__ int   g_bsums[512];
__device__ int2  g_edges[NNZ_MAX];                       // {col, val bits}, row-sorted
__device__ float g_X1[(size_t)N_NODES * D];
__device__ float g_X2[(size_t)N_NODES * D];
__device__ float g_S[(size_t)2 * B_MAX * D];             // online acc at sampled rows

// ---------------------------------------------------------------------------
// CSR construction
// ---------------------------------------------------------------------------

__global__ void hist_kernel(const int* __restrict__ row, int nnz,
                            int* __restrict__ counts) {
    for (int i = blockIdx.x * blockDim.x + threadIdx.x; i < nnz;
         i += gridDim.x * blockDim.x)
        atomicAdd(&counts[row[i]], 1);
}

__global__ void scan_block_kernel(const int* __restrict__ counts, int n,
                                  int* __restrict__ excl, int* __restrict__ bsums) {
    __shared__ int sd[1024];
    int tid = threadIdx.x;
    int i = blockIdx.x * 1024 + tid;
    int v = (i < n) ? counts[i] : 0;
    sd[tid] = v;
    __syncthreads();
    #pragma unroll
    for (int off = 1; off < 1024; off <<= 1) {
        int t = (tid >= off) ? sd[tid - off] : 0;
        __syncthreads();
        sd[tid] += t;
        __syncthreads();
    }
    if (i < n) excl[i] = sd[tid] - v;          // exclusive within block
    if (tid == 1023) bsums[blockIdx.x] = sd[1023];
}

__global__ void scan_top_kernel(int* __restrict__ bsums, int nb) {
    __shared__ int sd[512];
    int tid = threadIdx.x;
    int v = (tid < nb) ? bsums[tid] : 0;
    sd[tid] = v;
    __syncthreads();
    #pragma unroll
    for (int off = 1; off < 512; off <<= 1) {
        int t = (tid >= off) ? sd[tid - off] : 0;
        __syncthreads();
        sd[tid] += t;
        __syncthreads();
    }
    if (tid < nb) bsums[tid] = sd[tid] - v;    // exclusive block offsets
}

__global__ void scan_add_kernel(int* __restrict__ rowptr, int* __restrict__ cursor,
                                const int* __restrict__ bsums, int n, int nnz) {
    int i = blockIdx.x * 1024 + threadIdx.x;
    if (i < n) {
        int v = rowptr[i] + bsums[blockIdx.x];
        rowptr[i] = v;
        cursor[i] = v;
    }
    if (i == 0) rowptr[n] = nnz;
}

__global__ void scatter_kernel(const int* __restrict__ row, const int* __restrict__ col,
                               const float* __restrict__ val, int nnz,
                               int* __restrict__ cursor, int2* __restrict__ edges) {
    for (int i = blockIdx.x * blockDim.x + threadIdx.x; i < nnz;
         i += gridDim.x * blockDim.x) {
        int r = row[i];
        int pos = atomicAdd(&cursor[r], 1);
        edges[pos] = make_int2(col[i], __float_as_int(val[i]));
    }
}

// ---------------------------------------------------------------------------
// SpMM: one warp per output row. Edges preloaded 32-wide, broadcast by shfl.
// X_in addressed through a user/item pointer pair: for a unified array pass
// (base, base + usplit*D2).
// ---------------------------------------------------------------------------

__global__ void __launch_bounds__(256) spmm_kernel(
    const int* __restrict__ rowptr, const int2* __restrict__ edges,
    const float2* __restrict__ pu, const float2* __restrict__ pi,
    float2* __restrict__ xout, int nrows, int usplit)
{
    int w = (blockIdx.x * 256 + threadIdx.x) >> 5;
    if (w >= nrows) return;
    int lane = threadIdx.x & 31;
    int start = __ldg(&rowptr[w]);
    int end   = __ldg(&rowptr[w + 1]);
    float2 acc = make_float2(0.f, 0.f);

    for (int base = start; base < end; base += 32) {
        int2 ev = make_int2(0, 0);
        if (base + lane < end) ev = edges[base + lane];
        int cnt = min(32, end - base);
        #pragma unroll 4
        for (int j = 0; j < cnt; j++) {
            int   c = __shfl_sync(0xffffffffu, ev.x, j);
            float v = __int_as_float(__shfl_sync(0xffffffffu, ev.y, j));
            const float2* src = (c < usplit) ? (pu + (size_t)c * D2)
                                             : (pi + (size_t)(c - usplit) * D2);
            float2 x = __ldg(src + lane);
            acc.x = fmaf(v, x.x, acc.x);
            acc.y = fmaf(v, x.y, acc.y);
        }
    }
    // streaming store: don't evict the L2-resident X_in with the output
    __stcs(&xout[(size_t)w * D2 + lane], acc);
}

// ---------------------------------------------------------------------------
// Layer-3 at sampled rows, fused with acc = 0.25*(ego + X1 + X2 + X3)
// ---------------------------------------------------------------------------

__global__ void __launch_bounds__(256) sampled_kernel(
    const int* __restrict__ rowptr, const int2* __restrict__ edges,
    const float2* __restrict__ x2,                    // unified [N] layer-2 out
    const float2* __restrict__ egou, const float2* __restrict__ egoi,
    const float2* __restrict__ x1,                    // unified [N] layer-1 out
    const int* __restrict__ user_idx, const int* __restrict__ item_idx,
    float2* __restrict__ dst_u, float2* __restrict__ dst_i,
    int b, int usplit)
{
    int s = (blockIdx.x * 256 + threadIdx.x) >> 5;
    if (s >= 2 * b) return;
    int lane = threadIdx.x & 31;
    int r = (s < b) ? __ldg(&user_idx[s]) : usplit + __ldg(&item_idx[s - b]);

    int start = __ldg(&rowptr[r]);
    int end   = __ldg(&rowptr[r + 1]);
    float2 acc = make_float2(0.f, 0.f);
    for (int base = start; base < end; base += 32) {
        int2 ev = make_int2(0, 0);
        if (base + lane < end) ev = edges[base + lane];
        int cnt = min(32, end - base);
        #pragma unroll 4
        for (int j = 0; j < cnt; j++) {
            int   c = __shfl_sync(0xffffffffu, ev.x, j);
            float v = __int_as_float(__shfl_sync(0xffffffffu, ev.y, j));
            float2 x = __ldg(x2 + (size_t)c * D2 + lane);
            acc.x = fmaf(v, x.x, acc.x);
            acc.y = fmaf(v, x.y, acc.y);
        }
    }
    float2 e  = (r < usplit) ? __ldg(&egou[(size_t)r * D2 + lane])
                             : __ldg(&egoi[(size_t)(r - usplit) * D2 + lane]);
    float2 a1 = __ldg(&x1[(size_t)r * D2 + lane]);
    float2 a2 = __ldg(&x2[(size_t)r * D2 + lane]);
    float2 res;
    res.x = 0.25f * (e.x + a1.x + a2.x + acc.x);
    res.y = 0.25f * (e.y + a1.y + a2.y + acc.y);
    float2* d = (s < b) ? (dst_u + (size_t)s * D2 + lane)
                        : (dst_i + (size_t)(s - b) * D2 + lane);
    *d = res;
}

// ---------------------------------------------------------------------------
// Linear head: out = S @ W^T + bias   (S: [2B,64], W: [64,64] row-major)
// ---------------------------------------------------------------------------

__global__ void __launch_bounds__(256) pred_kernel(
    const float* __restrict__ S, const float* __restrict__ W,
    const float* __restrict__ bias,
    float* __restrict__ out_u, float* __restrict__ out_i, int b)
{
    __shared__ float Wt[64][65];     // Wt[k][j] = W[j,k]  (transposed, pad)
    __shared__ float srow[4][64];
    __shared__ float sb[64];
    int tx = threadIdx.x, ty = threadIdx.y;
    int tid = ty * 64 + tx;
    for (int idx = tid; idx < 4096; idx += 256)
        Wt[idx & 63][idx >> 6] = W[idx];
    if (tid < 64) sb[tid] = bias[tid];
    int s = blockIdx.x * 4 + ty;
    srow[ty][tx] = S[(size_t)s * 64 + tx];
    __syncthreads();

    float acc = sb[tx];
    #pragma unroll
    for (int k = 0; k < 64; k++)
        acc = fmaf(srow[ty][k], Wt[k][tx], acc);

    float* d = (s < b) ? (out_u + (size_t)s * 64 + tx)
                       : (out_i + (size_t)(s - b) * 64 + tx);
    *d = acc;
}

// ---------------------------------------------------------------------------
// Launch
// ---------------------------------------------------------------------------

extern "C" void kernel_launch(void* const* d_in, const int* in_sizes, int n_in,
                              void* d_out, int out_size) {
    const float* ue_on   = (const float*)d_in[0];
    const float* ie_on   = (const float*)d_in[1];
    const float* ue_tg   = (const float*)d_in[2];
    const float* ie_tg   = (const float*)d_in[3];
    const float* adj_val = (const float*)d_in[4];
    const float* pred_w  = (const float*)d_in[5];
    const float* pred_b  = (const float*)d_in[6];
    const int*   adj_row = (const int*)d_in[7];
    const int*   adj_col = (const int*)d_in[8];
    const int*   user_idx = (const int*)d_in[9];
    const int*   item_idx = (const int*)d_in[10];

    int uN  = in_sizes[0] / D;
    int iN  = in_sizes[1] / D;
    int n   = uN + iN;
    int nnz = in_sizes[4];
    int b   = in_sizes[9];

    int *counts, *rowptr, *cursor, *bsums;
    int2* edges;
    float *x1, *x2, *S;
    cudaGetSymbolAddress((void**)&counts, g_counts);
    cudaGetSymbolAddress((void**)&rowptr, g_rowptr);
    cudaGetSymbolAddress((void**)&cursor, g_cursor);
    cudaGetSymbolAddress((void**)&bsums,  g_bsums);
    cudaGetSymbolAddress((void**)&edges,  g_edges);
    cudaGetSymbolAddress((void**)&x1,     g_X1);
    cudaGetSymbolAddress((void**)&x2,     g_X2);
    cudaGetSymbolAddress((void**)&S,      g_S);

    // --- CSR build ---
    cudaMemsetAsync(counts, 0, (size_t)n * sizeof(int), 0);
    hist_kernel<<<1024, 256>>>(adj_row, nnz, counts);
    int nb = (n + 1023) / 1024;
    scan_block_kernel<<<nb, 1024>>>(counts, n, rowptr, bsums);
    scan_top_kernel<<<1, 512>>>(bsums, nb);
    scan_add_kernel<<<nb, 1024>>>(rowptr, cursor, bsums, n, nnz);
    scatter_kernel<<<2048, 256>>>(adj_row, adj_col, adj_val, nnz, cursor, edges);

    int spmm_blocks = (n + 7) / 8;          // 8 warps (rows) per block
    int samp_blocks = (2 * b + 7) / 8;
    float* out = (float*)d_out;
    size_t BD = (size_t)b * D;

    // --- online encoding ---
    spmm_kernel<<<spmm_blocks, 256>>>(rowptr, edges,
        (const float2*)ue_on, (const float2*)ie_on, (float2*)x1, n, uN);
    spmm_kernel<<<spmm_blocks, 256>>>(rowptr, edges,
        (const float2*)x1, (const float2*)x1 + (size_t)uN * D2, (float2*)x2, n, uN);
    sampled_kernel<<<samp_blocks, 256>>>(rowptr, edges, (const float2*)x2,
        (const float2*)ue_on, (const float2*)ie_on, (const float2*)x1,
        user_idx, item_idx,
        (float2*)S, (float2*)(S + BD), b, uN);
    pred_kernel<<<(2 * b) / 4, dim3(64, 4)>>>(S, pred_w, pred_b,
        out /* u_pred */, out + 2 * BD /* i_pred */, b);

    // --- target encoding ---
    spmm_kernel<<<spmm_blocks, 256>>>(rowptr, edges,
        (const float2*)ue_tg, (const float2*)ie_tg, (float2*)x1, n, uN);
    spmm_kernel<<<spmm_blocks, 256>>>(rowptr, edges,
        (const float2*)x1, (const float2*)x1 + (size_t)uN * D2, (float2*)x2, n, uN);
    sampled_kernel<<<samp_blocks, 256>>>(rowptr, edges, (const float2*)x2,
        (const float2*)ue_tg, (const float2*)ie_tg, (const float2*)x1,
        user_idx, item_idx,
        (float2*)(out + BD) /* u_target */, (float2*)(out + 3 * BD) /* i_target */,
        b, uN);
}

// round 2
// speedup vs baseline: 1.4870x; 1.4870x over previous
#include <cuda_runtime.h>
#include <cuda_fp16.h>

// ---------------------------------------------------------------------------
// BUIR / LightGCN forward, fp16-fused version.
//   - Online+target embeddings interleaved per node: H[r] = [64 on | 64 tg] fp16
//     (256B per node row). One SpMM pass computes BOTH encodings' layers.
//   - Counting-sort edges into CSR each call (histogram + 2-level scan + scatter).
//   - X1 = A@ego, X2 = A@X1 full fused SpMM; layer 3 only at the 8192 sampled
//     rows, fused with acc = (ego + X1 + X2 + X3)/4 (ego read in exact fp32).
//   - Online acc -> 64x64 linear head; target acc -> straight to output.
// Output layout: [u_pred | u_target | i_pred | i_target], each [B,64] f32.
// ---------------------------------------------------------------------------

#define D        64
#define HROW     64          // half2 elements per node row (128 halfs)
#define N_NODES  300000
#define NNZ_MAX  6400000
#define B_MAX    4096

// Scratch (device globals — no allocation allowed in kernel_launch)
__device__ int     g_counts[N_NODES];
__device__ int     g_rowptr[N_NODES + 1];
__device__ int     g_cursor[N_NODES];
__device__ int     g_bsums[512];
__device__ int2    g_edges[NNZ_MAX];                    // {col, val bits}, row-sorted
__device__ __half2 g_H0[(size_t)N_NODES * HROW];        // ego     (on|tg fp16)
__device__ __half2 g_H1[(size_t)N_NODES * HROW];        // layer 1
__device__ __half2 g_H2[(size_t)N_NODES * HROW];        // layer 2
__device__ float   g_S[(size_t)2 * B_MAX * D];          // online acc at sampled rows

// ---------------------------------------------------------------------------
// ego -> interleaved fp16
// ---------------------------------------------------------------------------
__global__ void __launch_bounds__(256) convert_kernel(
    const float2* __restrict__ ue_on, const float2* __restrict__ ie_on,
    const float2* __restrict__ ue_tg, const float2* __restrict__ ie_tg,
    __half2* __restrict__ h0, int n, int usplit)
{
    int idx = blockIdx.x * 256 + threadIdx.x;           // over n*32 float2 slots
    if (idx >= n * 32) return;
    int r = idx >> 5;
    int k = idx & 31;
    float2 on, tg;
    if (r < usplit) {
        on = ue_on[(size_t)r * 32 + k];
        tg = ue_tg[(size_t)r * 32 + k];
    } else {
        on = ie_on[(size_t)(r - usplit) * 32 + k];
        tg = ie_tg[(size_t)(r - usplit) * 32 + k];
    }
    h0[(size_t)r * HROW + k]      = __floats2half2_rn(on.x, on.y);
    h0[(size_t)r * HROW + 32 + k] = __floats2half2_rn(tg.x, tg.y);
}

// ---------------------------------------------------------------------------
// CSR construction
// ---------------------------------------------------------------------------
__global__ void hist_kernel(const int* __restrict__ row, int nnz,
                            int* __restrict__ counts) {
    for (int i = blockIdx.x * blockDim.x + threadIdx.x; i < nnz;
         i += gridDim.x * blockDim.x)
        atomicAdd(&counts[row[i]], 1);
}

__global__ void scan_block_kernel(const int* __restrict__ counts, int n,
                                  int* __restrict__ excl, int* __restrict__ bsums) {
    __shared__ int sd[1024];
    int tid = threadIdx.x;
    int i = blockIdx.x * 1024 + tid;
    int v = (i < n) ? counts[i] : 0;
    sd[tid] = v;
    __syncthreads();
    #pragma unroll
    for (int off = 1; off < 1024; off <<= 1) {
        int t = (tid >= off) ? sd[tid - off] : 0;
        __syncthreads();
        sd[tid] += t;
        __syncthreads();
    }
    if (i < n) excl[i] = sd[tid] - v;
    if (tid == 1023) bsums[blockIdx.x] = sd[1023];
}

__global__ void scan_top_kernel(int* __restrict__ bsums, int nb) {
    __shared__ int sd[512];
    int tid = threadIdx.x;
    int v = (tid < nb) ? bsums[tid] : 0;
    sd[tid] = v;
    __syncthreads();
    #pragma unroll
    for (int off = 1; off < 512; off <<= 1) {
        int t = (tid >= off) ? sd[tid - off] : 0;
        __syncthreads();
        sd[tid] += t;
        __syncthreads();
    }
    if (tid < nb) bsums[tid] = sd[tid] - v;
}

__global__ void scan_add_kernel(int* __restrict__ rowptr, int* __restrict__ cursor,
                                const int* __restrict__ bsums, int n, int nnz) {
    int i = blockIdx.x * 1024 + threadIdx.x;
    if (i < n) {
        int v = rowptr[i] + bsums[blockIdx.x];
        rowptr[i] = v;
        cursor[i] = v;
    }
    if (i == 0) rowptr[n] = nnz;
}

__global__ void scatter_kernel(const int* __restrict__ row, const int* __restrict__ col,
                               const float* __restrict__ val, int nnz,
                               int* __restrict__ cursor, int2* __restrict__ edges) {
    for (int i = blockIdx.x * blockDim.x + threadIdx.x; i < nnz;
         i += gridDim.x * blockDim.x) {
        int r = row[i];
        int pos = atomicAdd(&cursor[r], 1);
        edges[pos] = make_int2(col[i], __float_as_int(val[i]));
    }
}

// ---------------------------------------------------------------------------
// Fused SpMM (both encodings in one pass): one warp per output row.
// Edges preloaded 32-wide, broadcast by shfl. Per edge: two coalesced 128B
// half2 loads (online half + target half of the 256B node row).
// ---------------------------------------------------------------------------
__global__ void __launch_bounds__(256) spmm_fused_kernel(
    const int* __restrict__ rowptr, const int2* __restrict__ edges,
    const __half2* __restrict__ xin, __half2* __restrict__ xout, int nrows)
{
    int w = (blockIdx.x * 256 + threadIdx.x) >> 5;
    if (w >= nrows) return;
    int lane = threadIdx.x & 31;
    int start = __ldg(&rowptr[w]);
    int end   = __ldg(&rowptr[w + 1]);
    float2 aon = make_float2(0.f, 0.f);
    float2 atg = make_float2(0.f, 0.f);

    for (int base = start; base < end; base += 32) {
        int2 ev = make_int2(0, 0);
        if (base + lane < end) ev = edges[base + lane];
        int cnt = min(32, end - base);
        #pragma unroll 4
        for (int j = 0; j < cnt; j++) {
            int   c = __shfl_sync(0xffffffffu, ev.x, j);
            float v = __int_as_float(__shfl_sync(0xffffffffu, ev.y, j));
            const __half2* src = xin + (size_t)c * HROW;
            float2 a = __half22float2(__ldg(src + lane));
            float2 b = __half22float2(__ldg(src + 32 + lane));
            aon.x = fmaf(v, a.x, aon.x);
            aon.y = fmaf(v, a.y, aon.y);
            atg.x = fmaf(v, b.x, atg.x);
            atg.y = fmaf(v, b.y, atg.y);
        }
    }
    // streaming stores: keep xin L2-resident
    __stcs(&xout[(size_t)w * HROW + lane],      __floats2half2_rn(aon.x, aon.y));
    __stcs(&xout[(size_t)w * HROW + 32 + lane], __floats2half2_rn(atg.x, atg.y));
}

// ---------------------------------------------------------------------------
// Layer-3 at sampled rows (both encodings), fused with
// acc = 0.25*(ego_fp32 + X1 + X2 + X3). Online acc -> S, target acc -> out.
// ---------------------------------------------------------------------------
__global__ void __launch_bounds__(256) sampled_fused_kernel(
    const int* __restrict__ rowptr, const int2* __restrict__ edges,
    const __half2* __restrict__ h1, const __half2* __restrict__ h2,
    const float2* __restrict__ ue_on, const float2* __restrict__ ie_on,
    const float2* __restrict__ ue_tg, const float2* __restrict__ ie_tg,
    const int* __restrict__ user_idx, const int* __restrict__ item_idx,
    float2* __restrict__ s_on,          // [2B,64] fp32 online acc (pred input)
    float2* __restrict__ out_utg, float2* __restrict__ out_itg,
    int b, int usplit)
{
    int s = (blockIdx.x * 256 + threadIdx.x) >> 5;
    if (s >= 2 * b) return;
    int lane = threadIdx.x & 31;
    int r = (s < b) ? __ldg(&user_idx[s]) : usplit + __ldg(&item_idx[s - b]);

    int start = __ldg(&rowptr[r]);
    int end   = __ldg(&rowptr[r + 1]);
    float2 aon = make_float2(0.f, 0.f);
    float2 atg = make_float2(0.f, 0.f);
    for (int base = start; base < end; base += 32) {
        int2 ev = make_int2(0, 0);
        if (base + lane < end) ev = edges[base + lane];
        int cnt = min(32, end - base);
        #pragma unroll 4
        for (int j = 0; j < cnt; j++) {
            int   c = __shfl_sync(0xffffffffu, ev.x, j);
            float v = __int_as_float(__shfl_sync(0xffffffffu, ev.y, j));
            const __half2* src = h2 + (size_t)c * HROW;
            float2 a = __half22float2(__ldg(src + lane));
            float2 t = __half22float2(__ldg(src + 32 + lane));
            aon.x = fmaf(v, a.x, aon.x);
            aon.y = fmaf(v, a.y, aon.y);
            atg.x = fmaf(v, t.x, atg.x);
            atg.y = fmaf(v, t.y, atg.y);
        }
    }

    float2 e_on = (r < usplit) ? __ldg(&ue_on[(size_t)r * 32 + lane])
                               : __ldg(&ie_on[(size_t)(r - usplit) * 32 + lane]);
    float2 e_tg = (r < usplit) ? __ldg(&ue_tg[(size_t)r * 32 + lane])
                               : __ldg(&ie_tg[(size_t)(r - usplit) * 32 + lane]);
    float2 x1on = __half22float2(__ldg(h1 + (size_t)r * HROW + lane));
    float2 x1tg = __half22float2(__ldg(h1 + (size_t)r * HROW + 32 + lane));
    float2 x2on = __half22float2(__ldg(h2 + (size_t)r * HROW + lane));
    float2 x2tg = __half22float2(__ldg(h2 + (size_t)r * HROW + 32 + lane));

    float2 ron, rtg;
    ron.x = 0.25f * (e_on.x + x1on.x + x2on.x + aon.x);
    ron.y = 0.25f * (e_on.y + x1on.y + x2on.y + aon.y);
    rtg.x = 0.25f * (e_tg.x + x1tg.x + x2tg.x + atg.x);
    rtg.y = 0.25f * (e_tg.y + x1tg.y + x2tg.y + atg.y);

    s_on[(size_t)s * 32 + lane] = ron;
    float2* dtg = (s < b) ? (out_utg + (size_t)s * 32 + lane)
                          : (out_itg + (size_t)(s - b) * 32 + lane);
    *dtg = rtg;
}

// ---------------------------------------------------------------------------
// Linear head: out = S @ W^T + bias   (S: [2B,64], W: [64,64] row-major)
// ---------------------------------------------------------------------------
__global__ void __launch_bounds__(256) pred_kernel(
    const float* __restrict__ S, const float* __restrict__ W,
    const float* __restrict__ bias,
    float* __restrict__ out_u, float* __restrict__ out_i, int b)
{
    __shared__ float Wt[64][65];
    __shared__ float srow[4][64];
    __shared__ float sb[64];
    int tx = threadIdx.x, ty = threadIdx.y;
    int tid = ty * 64 + tx;
    for (int idx = tid; idx < 4096; idx += 256)
        Wt[idx & 63][idx >> 6] = W[idx];
    if (tid < 64) sb[tid] = bias[tid];
    int s = blockIdx.x * 4 + ty;
    srow[ty][tx] = S[(size_t)s * 64 + tx];
    __syncthreads();

    float acc = sb[tx];
    #pragma unroll
    for (int k = 0; k < 64; k++)
        acc = fmaf(srow[ty][k], Wt[k][tx], acc);

    float* d = (s < b) ? (out_u + (size_t)s * 64 + tx)
                       : (out_i + (size_t)(s - b) * 64 + tx);
    *d = acc;
}

// ---------------------------------------------------------------------------
// Launch
// ---------------------------------------------------------------------------
extern "C" void kernel_launch(void* const* d_in, const int* in_sizes, int n_in,
                              void* d_out, int out_size) {
    const float* ue_on   = (const float*)d_in[0];
    const float* ie_on   = (const float*)d_in[1];
    const float* ue_tg   = (const float*)d_in[2];
    const float* ie_tg   = (const float*)d_in[3];
    const float* adj_val = (const float*)d_in[4];
    const float* pred_w  = (const float*)d_in[5];
    const float* pred_b  = (const float*)d_in[6];
    const int*   adj_row = (const int*)d_in[7];
    const int*   adj_col = (const int*)d_in[8];
    const int*   user_idx = (const int*)d_in[9];
    const int*   item_idx = (const int*)d_in[10];

    int uN  = in_sizes[0] / D;
    int iN  = in_sizes[1] / D;
    int n   = uN + iN;
    int nnz = in_sizes[4];
    int b   = in_sizes[9];

    int *counts, *rowptr, *cursor, *bsums;
    int2* edges;
    __half2 *h0, *h1, *h2;
    float* S;
    cudaGetSymbolAddress((void**)&counts, g_counts);
    cudaGetSymbolAddress((void**)&rowptr, g_rowptr);
    cudaGetSymbolAddress((void**)&cursor, g_cursor);
    cudaGetSymbolAddress((void**)&bsums,  g_bsums);
    cudaGetSymbolAddress((void**)&edges,  g_edges);
    cudaGetSymbolAddress((void**)&h0,     g_H0);
    cudaGetSymbolAddress((void**)&h1,     g_H1);
    cudaGetSymbolAddress((void**)&h2,     g_H2);
    cudaGetSymbolAddress((void**)&S,      g_S);

    // --- CSR build + ego conversion ---
    cudaMemsetAsync(counts, 0, (size_t)n * sizeof(int), 0);
    hist_kernel<<<1024, 256>>>(adj_row, nnz, counts);
    int nb = (n + 1023) / 1024;
    scan_block_kernel<<<nb, 1024>>>(counts, n, rowptr, bsums);
    scan_top_kernel<<<1, 512>>>(bsums, nb);
    scan_add_kernel<<<nb, 1024>>>(rowptr, cursor, bsums, n, nnz);
    scatter_kernel<<<2048, 256>>>(adj_row, adj_col, adj_val, nnz, cursor, edges);
    convert_kernel<<<(n * 32 + 255) / 256, 256>>>(
        (const float2*)ue_on, (const float2*)ie_on,
        (const float2*)ue_tg, (const float2*)ie_tg, h0, n, uN);

    int spmm_blocks = (n + 7) / 8;
    int samp_blocks = (2 * b + 7) / 8;
    float* out = (float*)d_out;
    size_t BD = (size_t)b * D;

    // --- both encodings in fused passes ---
    spmm_fused_kernel<<<spmm_blocks, 256>>>(rowptr, edges, h0, h1, n);
    spmm_fused_kernel<<<spmm_blocks, 256>>>(rowptr, edges, h1, h2, n);
    sampled_fused_kernel<<<samp_blocks, 256>>>(rowptr, edges, h1, h2,
        (const float2*)ue_on, (const float2*)ie_on,
        (const float2*)ue_tg, (const float2*)ie_tg,
        user_idx, item_idx,
        (float2*)S,
        (float2*)(out + BD)      /* u_target */,
        (float2*)(out + 3 * BD)  /* i_target */,
        b, uN);
    pred_kernel<<<(2 * b) / 4, dim3(64, 4)>>>(S, pred_w, pred_b,
        out /* u_pred */, out + 2 * BD /* i_pred */, b);
}

// round 3
// speedup vs baseline: 1.6511x; 1.1104x over previous
#include <cuda_runtime.h>
#include <cuda_fp16.h>

// ---------------------------------------------------------------------------
// BUIR / LightGCN forward, fp16-fused, uint4-gather version.
//   - Online+target embeddings interleaved per node: H[r] = [64 on | 64 tg]
//     fp16 = 256B row. One SpMM pass computes BOTH encodings' layers.
//   - CSR by counting sort. g_counts is re-zeroed by scan_add for the next
//     call (globals start zero at module load), so no memset needed.
//   - convert (ego->fp16) fused into the hist launch (independent work).
//   - SpMM: warp per row, 2 edges per step (half-warp each), one LDG.128
//     per lane covering 16B of the row; shfl-xor(16) reduction at the end.
//   - Layer 3 only at sampled rows, fused with acc=(ego+X1+X2+X3)/4.
// Output layout: [u_pred | u_target | i_pred | i_target], each [B,64] f32.
// ---------------------------------------------------------------------------

#define D        64
#define HROW     64          // half2 per node row (128 halfs = 256B)
#define N_NODES  300000
#define NNZ_MAX  6400000
#define B_MAX    4096
#define HIST_BLOCKS 1024

// Scratch (device globals — no allocation allowed in kernel_launch)
__device__ int     g_counts[N_NODES];        // zero at load; re-zeroed each call
__device__ int     g_rowptr[N_NODES + 1];
__device__ int     g_cursor[N_NODES];
__device__ int     g_bsums[512];
__device__ int2    g_edges[NNZ_MAX];         // {col, val bits}, row-sorted
__device__ __half2 g_H0[(size_t)N_NODES * HROW];
__device__ __half2 g_H1[(size_t)N_NODES * HROW];
__device__ __half2 g_H2[(size_t)N_NODES * HROW];
__device__ float   g_S[(size_t)2 * B_MAX * D];

static __device__ __forceinline__ unsigned h2_as_u(__half2 h) {
    return *reinterpret_cast<unsigned*>(&h);
}
static __device__ __forceinline__ __half2 u_as_h2(unsigned u) {
    return *reinterpret_cast<__half2*>(&u);
}

// ---------------------------------------------------------------------------
// Fused: histogram (blocks [0,HIST_BLOCKS)) + ego->fp16 convert (rest)
// ---------------------------------------------------------------------------
__global__ void __launch_bounds__(256) hist_convert_kernel(
    const int* __restrict__ row, int nnz, int* __restrict__ counts,
    const float2* __restrict__ ue_on, const float2* __restrict__ ie_on,
    const float2* __restrict__ ue_tg, const float2* __restrict__ ie_tg,
    __half2* __restrict__ h0, int n, int usplit)
{
    if (blockIdx.x < HIST_BLOCKS) {
        for (int i = blockIdx.x * 256 + threadIdx.x; i < nnz;
             i += HIST_BLOCKS * 256)
            atomicAdd(&counts[__ldcs(&row[i])], 1);
    } else {
        int idx = (blockIdx.x - HIST_BLOCKS) * 256 + threadIdx.x;
        if (idx >= n * 32) return;
        int r = idx >> 5;
        int k = idx & 31;
        float2 on, tg;
        if (r < usplit) {
            on = ue_on[(size_t)r * 32 + k];
            tg = ue_tg[(size_t)r * 32 + k];
        } else {
            on = ie_on[(size_t)(r - usplit) * 32 + k];
            tg = ie_tg[(size_t)(r - usplit) * 32 + k];
        }
        h0[(size_t)r * HROW + k]      = __floats2half2_rn(on.x, on.y);
        h0[(size_t)r * HROW + 32 + k] = __floats2half2_rn(tg.x, tg.y);
    }
}

// ---------------------------------------------------------------------------
// CSR scans / scatter
// ---------------------------------------------------------------------------
__global__ void scan_block_kernel(const int* __restrict__ counts, int n,
                                  int* __restrict__ excl, int* __restrict__ bsums) {
    __shared__ int sd[1024];
    int tid = threadIdx.x;
    int i = blockIdx.x * 1024 + tid;
    int v = (i < n) ? counts[i] : 0;
    sd[tid] = v;
    __syncthreads();
    #pragma unroll
    for (int off = 1; off < 1024; off <<= 1) {
        int t = (tid >= off) ? sd[tid - off] : 0;
        __syncthreads();
        sd[tid] += t;
        __syncthreads();
    }
    if (i < n) excl[i] = sd[tid] - v;
    if (tid == 1023) bsums[blockIdx.x] = sd[1023];
}

__global__ void scan_top_kernel(int* __restrict__ bsums, int nb) {
    __shared__ int sd[512];
    int tid = threadIdx.x;
    int v = (tid < nb) ? bsums[tid] : 0;
    sd[tid] = v;
    __syncthreads();
    #pragma unroll
    for (int off = 1; off < 512; off <<= 1) {
        int t = (tid >= off) ? sd[tid - off] : 0;
        __syncthreads();
        sd[tid] += t;
        __syncthreads();
    }
    if (tid < nb) bsums[tid] = sd[tid] - v;
}

// Also re-zeroes counts for the NEXT call (scan_block already consumed them).
__global__ void scan_add_kernel(int* __restrict__ rowptr, int* __restrict__ cursor,
                                int* __restrict__ counts,
                                const int* __restrict__ bsums, int n, int nnz) {
    int i = blockIdx.x * 1024 + threadIdx.x;
    if (i < n) {
        int v = rowptr[i] + bsums[blockIdx.x];
        rowptr[i] = v;
        cursor[i] = v;
        counts[i] = 0;
    }
    if (i == 0) rowptr[n] = nnz;
}

__global__ void scatter_kernel(const int* __restrict__ row, const int* __restrict__ col,
                               const float* __restrict__ val, int nnz,
                               int* __restrict__ cursor, int2* __restrict__ edges) {
    for (int i = blockIdx.x * blockDim.x + threadIdx.x; i < nnz;
         i += gridDim.x * blockDim.x) {
        int r = __ldcs(&row[i]);
        int pos = atomicAdd(&cursor[r], 1);
        edges[pos] = make_int2(__ldcs(&col[i]), __float_as_int(__ldcs(&val[i])));
    }
}

// ---------------------------------------------------------------------------
// Fused SpMM: warp per row. 2 edges per step (half-warp 0 -> edge j,
// half-warp 1 -> edge j+1). Each lane: one LDG.128 covering 16B of the 256B
// node row. Partials combined with shfl_xor(16); lanes 0-15 store uint4.
// ---------------------------------------------------------------------------
__global__ void __launch_bounds__(256) spmm_fused_kernel(
    const int* __restrict__ rowptr, const int2* __restrict__ edges,
    const __half2* __restrict__ xin, __half2* __restrict__ xout, int nrows)
{
    int w = (blockIdx.x * 256 + threadIdx.x) >> 5;
    if (w >= nrows) return;
    int lane = threadIdx.x & 31;
    int half = lane >> 4;          // which edge of the pair
    int hl   = lane & 15;          // 16B segment index within the row
    int start = __ldg(&rowptr[w]);
    int end   = __ldg(&rowptr[w + 1]);

    float2 acc[4];
    #pragma unroll
    for (int k = 0; k < 4; k++) acc[k] = make_float2(0.f, 0.f);

    const char* xbase = (const char*)xin;

    for (int base = start; base < end; base += 32) {
        int2 ev = make_int2(0, 0);                 // col 0 / val 0 is a safe pad
        if (base + lane < end) ev = __ldcs(&edges[base + lane]);
        int cnt = min(32, end - base);
        for (int j = 0; j < cnt; j += 2) {
            int src = j + half;                    // half 1 reads pad if j+1>=cnt
            int   c = __shfl_sync(0xffffffffu, ev.x, src);
            float v = __int_as_float(__shfl_sync(0xffffffffu, ev.y, src));
            uint4 raw = __ldg((const uint4*)(xbase + (size_t)c * 256 + hl * 16));
            float2 f0 = __half22float2(u_as_h2(raw.x));
            float2 f1 = __half22float2(u_as_h2(raw.y));
            float2 f2 = __half22float2(u_as_h2(raw.z));
            float2 f3 = __half22float2(u_as_h2(raw.w));
            acc[0].x = fmaf(v, f0.x, acc[0].x);
            acc[0].y = fmaf(v, f0.y, acc[0].y);
            acc[1].x = fmaf(v, f1.x, acc[1].x);
            acc[1].y = fmaf(v, f1.y, acc[1].y);
            acc[2].x = fmaf(v, f2.x, acc[2].x);
            acc[2].y = fmaf(v, f2.y, acc[2].y);
            acc[3].x = fmaf(v, f3.x, acc[3].x);
            acc[3].y = fmaf(v, f3.y, acc[3].y);
        }
    }

    // combine the two half-warps' edge partials (same byte ranges)
    #pragma unroll
    for (int k = 0; k < 4; k++) {
        acc[k].x += __shfl_xor_sync(0xffffffffu, acc[k].x, 16);
        acc[k].y += __shfl_xor_sync(0xffffffffu, acc[k].y, 16);
    }
    if (lane < 16) {
        uint4 o;
        o.x = h2_as_u(__floats2half2_rn(acc[0].x, acc[0].y));
        o.y = h2_as_u(__floats2half2_rn(acc[1].x, acc[1].y));
        o.z = h2_as_u(__floats2half2_rn(acc[2].x, acc[2].y));
        o.w = h2_as_u(__floats2half2_rn(acc[3].x, acc[3].y));
        __stcs((uint4*)((char*)xout + (size_t)w * 256 + hl * 16), o);
    }
}

// ---------------------------------------------------------------------------
// Layer-3 at sampled rows (both encodings), fused with
// acc = 0.25*(ego_fp32 + X1 + X2 + X3). Online acc -> S, target acc -> out.
// ---------------------------------------------------------------------------
__global__ void __launch_bounds__(256) sampled_fused_kernel(
    const int* __restrict__ rowptr, const int2* __restrict__ edges,
    const __half2* __restrict__ h1, const __half2* __restrict__ h2,
    const float2* __restrict__ ue_on, const float2* __restrict__ ie_on,
    const float2* __restrict__ ue_tg, const float2* __restrict__ ie_tg,
    const int* __restrict__ user_idx, const int* __restrict__ item_idx,
    float2* __restrict__ s_on,
    float2* __restrict__ out_utg, float2* __restrict__ out_itg,
    int b, int usplit)
{
    int s = (blockIdx.x * 256 + threadIdx.x) >> 5;
    if (s >= 2 * b) return;
    int lane = threadIdx.x & 31;
    int r = (s < b) ? __ldg(&user_idx[s]) : usplit + __ldg(&item_idx[s - b]);

    int start = __ldg(&rowptr[r]);
    int end   = __ldg(&rowptr[r + 1]);
    float2 aon = make_float2(0.f, 0.f);
    float2 atg = make_float2(0.f, 0.f);
    for (int base = start; base < end; base += 32) {
        int2 ev = make_int2(0, 0);
        if (base + lane < end) ev = edges[base + lane];
        int cnt = min(32, end - base);
        #pragma unroll 4
        for (int j = 0; j < cnt; j++) {
            int   c = __shfl_sync(0xffffffffu, ev.x, j);
            float v = __int_as_float(__shfl_sync(0xffffffffu, ev.y, j));
            const __half2* src = h2 + (size_t)c * HROW;
            float2 a = __half22float2(__ldg(src + lane));
            float2 t = __half22float2(__ldg(src + 32 + lane));
            aon.x = fmaf(v, a.x, aon.x);
            aon.y = fmaf(v, a.y, aon.y);
            atg.x = fmaf(v, t.x, atg.x);
            atg.y = fmaf(v, t.y, atg.y);
        }
    }

    float2 e_on = (r < usplit) ? __ldg(&ue_on[(size_t)r * 32 + lane])
                               : __ldg(&ie_on[(size_t)(r - usplit) * 32 + lane]);
    float2 e_tg = (r < usplit) ? __ldg(&ue_tg[(size_t)r * 32 + lane])
                               : __ldg(&ie_tg[(size_t)(r - usplit) * 32 + lane]);
    float2 x1on = __half22float2(__ldg(h1 + (size_t)r * HROW + lane));
    float2 x1tg = __half22float2(__ldg(h1 + (size_t)r * HROW + 32 + lane));
    float2 x2on = __half22float2(__ldg(h2 + (size_t)r * HROW + lane));
    float2 x2tg = __half22float2(__ldg(h2 + (size_t)r * HROW + 32 + lane));

    float2 ron, rtg;
    ron.x = 0.25f * (e_on.x + x1on.x + x2on.x + aon.x);
    ron.y = 0.25f * (e_on.y + x1on.y + x2on.y + aon.y);
    rtg.x = 0.25f * (e_tg.x + x1tg.x + x2tg.x + atg.x);
    rtg.y = 0.25f * (e_tg.y + x1tg.y + x2tg.y + atg.y);

    s_on[(size_t)s * 32 + lane] = ron;
    float2* dtg = (s < b) ? (out_utg + (size_t)s * 32 + lane)
                          : (out_itg + (size_t)(s - b) * 32 + lane);
    *dtg = rtg;
}

// ---------------------------------------------------------------------------
// Linear head: out = S @ W^T + bias   (S: [2B,64], W: [64,64] row-major)
// ---------------------------------------------------------------------------
__global__ void __launch_bounds__(256) pred_kernel(
    const float* __restrict__ S, const float* __restrict__ W,
    const float* __restrict__ bias,
    float* __restrict__ out_u, float* __restrict__ out_i, int b)
{
    __shared__ float Wt[64][65];
    __shared__ float srow[4][64];
    __shared__ float sb[64];
    int tx = threadIdx.x, ty = threadIdx.y;
    int tid = ty * 64 + tx;
    for (int idx = tid; idx < 4096; idx += 256)
        Wt[idx & 63][idx >> 6] = W[idx];
    if (tid < 64) sb[tid] = bias[tid];
    int s = blockIdx.x * 4 + ty;
    srow[ty][tx] = S[(size_t)s * 64 + tx];
    __syncthreads();

    float acc = sb[tx];
    #pragma unroll
    for (int k = 0; k < 64; k++)
        acc = fmaf(srow[ty][k], Wt[k][tx], acc);

    float* d = (s < b) ? (out_u + (size_t)s * 64 + tx)
                       : (out_i + (size_t)(s - b) * 64 + tx);
    *d = acc;
}

// ---------------------------------------------------------------------------
// Launch
// ---------------------------------------------------------------------------
extern "C" void kernel_launch(void* const* d_in, const int* in_sizes, int n_in,
                              void* d_out, int out_size) {
    const float* ue_on   = (const float*)d_in[0];
    const float* ie_on   = (const float*)d_in[1];
    const float* ue_tg   = (const float*)d_in[2];
    const float* ie_tg   = (const float*)d_in[3];
    const float* adj_val = (const float*)d_in[4];
    const float* pred_w  = (const float*)d_in[5];
    const float* pred_b  = (const float*)d_in[6];
    const int*   adj_row = (const int*)d_in[7];
    const int*   adj_col = (const int*)d_in[8];
    const int*   user_idx = (const int*)d_in[9];
    const int*   item_idx = (const int*)d_in[10];

    int uN  = in_sizes[0] / D;
    int iN  = in_sizes[1] / D;
    int n   = uN + iN;
    int nnz = in_sizes[4];
    int b   = in_sizes[9];

    int *counts, *rowptr, *cursor, *bsums;
    int2* edges;
    __half2 *h0, *h1, *h2;
    float* S;
    cudaGetSymbolAddress((void**)&counts, g_counts);
    cudaGetSymbolAddress((void**)&rowptr, g_rowptr);
    cudaGetSymbolAddress((void**)&cursor, g_cursor);
    cudaGetSymbolAddress((void**)&bsums,  g_bsums);
    cudaGetSymbolAddress((void**)&edges,  g_edges);
    cudaGetSymbolAddress((void**)&h0,     g_H0);
    cudaGetSymbolAddress((void**)&h1,     g_H1);
    cudaGetSymbolAddress((void**)&h2,     g_H2);
    cudaGetSymbolAddress((void**)&S,      g_S);

    // --- CSR build (counts pre-zeroed by previous call / module load) ---
    int conv_blocks = (n * 32 + 255) / 256;
    hist_convert_kernel<<<HIST_BLOCKS + conv_blocks, 256>>>(
        adj_row, nnz, counts,
        (const float2*)ue_on, (const float2*)ie_on,
        (const float2*)ue_tg, (const float2*)ie_tg, h0, n, uN);
    int nb = (n + 1023) / 1024;
    scan_block_kernel<<<nb, 1024>>>(counts, n, rowptr, bsums);
    scan_top_kernel<<<1, 512>>>(bsums, nb);
    scan_add_kernel<<<nb, 1024>>>(rowptr, cursor, counts, bsums, n, nnz);
    scatter_kernel<<<2048, 256>>>(adj_row, adj_col, adj_val, nnz, cursor, edges);

    int spmm_blocks = (n + 7) / 8;
    int samp_blocks = (2 * b + 7) / 8;
    float* out = (float*)d_out;
    size_t BD = (size_t)b * D;

    spmm_fused_kernel<<<spmm_blocks, 256>>>(rowptr, edges, h0, h1, n);
    spmm_fused_kernel<<<spmm_blocks, 256>>>(rowptr, edges, h1, h2, n);
    sampled_fused_kernel<<<samp_blocks, 256>>>(rowptr, edges, h1, h2,
        (const float2*)ue_on, (const float2*)ie_on,
        (const float2*)ue_tg, (const float2*)ie_tg,
        user_idx, item_idx,
        (float2*)S,
        (float2*)(out + BD),
        (float2*)(out + 3 * BD),
        b, uN);
    pred_kernel<<<(2 * b) / 4, dim3(64, 4)>>>(S, pred_w, pred_b,
        out, out + 2 * BD, b);
}